// round 15
// baseline (speedup 1.0000x reference)
#include <cuda_runtime.h>
#include <cuda_fp16.h>
#include <math.h>

#define NN 20000
#define NE 640000

typedef unsigned long long u64;
typedef unsigned int u32;
typedef unsigned short u16;

// ---------------- scratch (device globals) ----------------
__device__ __align__(16) float g_xenc[NN * 64];
__device__ __align__(16) float g_x1[NN * 64];
__device__ __align__(16) float g_h1[NN * 64];
__device__ __align__(16) __half g_Pa[NN * 128];   // fp16 Pa
__device__ __align__(16) __half g_Pb[NN * 128];   // fp16 Pb
__device__ __align__(16) float g_nd0[NN * 128];
__device__ __align__(16) float g_nd1[NN * 128];
__device__ __align__(16) float g_msg0[(size_t)NE * 64];

// ---------------- f32x2 helpers ----------------
static __device__ __forceinline__ u64 fma2(u64 a, u64 b, u64 c) {
    u64 d; asm("fma.rn.f32x2 %0,%1,%2,%3;" : "=l"(d) : "l"(a), "l"(b), "l"(c)); return d;
}
static __device__ __forceinline__ u64 add2(u64 a, u64 b) {
    u64 d; asm("add.rn.f32x2 %0,%1,%2;" : "=l"(d) : "l"(a), "l"(b)); return d;
}
static __device__ __forceinline__ u64 mul2(u64 a, u64 b) {
    u64 d; asm("mul.rn.f32x2 %0,%1,%2;" : "=l"(d) : "l"(a), "l"(b)); return d;
}
static __device__ __forceinline__ u64 pack2(float lo, float hi) {
    u64 d; asm("mov.b64 %0,{%1,%2};" : "=l"(d) : "f"(lo), "f"(hi)); return d;
}
static __device__ __forceinline__ void unpack2(u64 a, float& lo, float& hi) {
    asm("mov.b64 {%0,%1},%2;" : "=f"(lo), "=f"(hi) : "l"(a));
}
static __device__ __forceinline__ float wsum(float v) {
#pragma unroll
    for (int o = 16; o; o >>= 1) v += __shfl_xor_sync(0xffffffffu, v, o);
    return v;
}
static __device__ __forceinline__ u32 smem_u32(const void* p) {
    u32 a; asm("{ .reg .u64 t; cvta.to.shared.u64 t, %1; cvt.u32.u64 %0, t; }" : "=r"(a) : "l"(p));
    return a;
}
static __device__ __forceinline__ u32 packh2(float x, float y) {
    __half hx = __float2half_rn(x), hy = __float2half_rn(y);
    return (u32)__half_as_ushort(hx) | ((u32)__half_as_ushort(hy) << 16);
}
static __device__ __forceinline__ float2 h2f2(u32 v) {
    __half2 h = *(__half2*)&v;
    return __half22float2(h);
}

#define LDSM4(r0, r1, r2, r3, a)                                             \
    asm volatile("ldmatrix.sync.aligned.m8n8.x4.shared.b16 {%0,%1,%2,%3}, [%4];" \
                 : "=r"(r0), "=r"(r1), "=r"(r2), "=r"(r3) : "r"(a))
#define MMAH(d, a0, a1, a2, a3, b0, b1)                                      \
    asm volatile("mma.sync.aligned.m16n8k16.row.col.f32.f16.f16.f32 "        \
                 "{%0,%1,%2,%3}, {%4,%5,%6,%7}, {%8,%9}, {%0,%1,%2,%3};"     \
                 : "+f"((d)[0]), "+f"((d)[1]), "+f"((d)[2]), "+f"((d)[3])    \
                 : "r"(a0), "r"(a1), "r"(a2), "r"(a3), "r"(b0), "r"(b1))

// ---------------- k_edge smem layout (bytes) ----------------
#define SO_W1T   0         // [128h][64k] fp16, stride 144  (18432)
#define SO_W2T   18432     // [64c][128k] fp16, stride 272  (17408)
#define SO_SB2   35840     // float[64]
#define SO_SEB   36096     // u64[32]
#define SO_SGP   36352
#define SO_SBBP  36608
#define SO_EEW   36864     // u64[512]
#define SO_WARP  40960     // per-warp regions
#define PW_BYTES 4608
#define PO_EAH   0         // [16e][64k] fp16, stride 144 (2304)
#define PO_HB    2304      // 2 slots x 768 (hi only)
#define PO_NDT   0         // ndt[8][136] f32 (4352) ALIASES EAH+HB (disjoint liveness)
#define NWARPS_E 8
#define SM_EDGE_BYTES (40960 + NWARPS_E * PW_BYTES)   // 77824  -> 2 CTAs/SM

// ---------------- zero accumulators ----------------
__global__ void k_zero() {
    int i = blockIdx.x * blockDim.x + threadIdx.x;
    if (i < NN * 128 / 4) {
        float4 z = make_float4(0.f, 0.f, 0.f, 0.f);
        ((float4*)g_nd0)[i] = z;
        ((float4*)g_nd1)[i] = z;
    }
}

// ---------------- node encoder ----------------
__global__ void __launch_bounds__(256) k_encode(
    const float* __restrict__ x, const float* __restrict__ enc_w,
    const float* __restrict__ enc_b, const float* __restrict__ enc_g,
    const float* __restrict__ enc_bb)
{
    extern __shared__ float sm[];
    for (int i = threadIdx.x; i < 96 * 64; i += blockDim.x) sm[i] = enc_w[i];
    __syncthreads();
    int l = threadIdx.x & 31;
    int warp = (blockIdx.x * blockDim.x + threadIdx.x) >> 5;
    int nwarps = (gridDim.x * blockDim.x) >> 5;
    float b0 = enc_b[l], b1v = enc_b[l + 32];
    float g0 = enc_g[l], g1 = enc_g[l + 32];
    float bb0 = enc_bb[l], bb1 = enc_bb[l + 32];
    for (int n = warp; n < NN; n += nwarps) {
        float xa = x[(size_t)n * 96 + l];
        float xb = x[(size_t)n * 96 + 32 + l];
        float xc = x[(size_t)n * 96 + 64 + l];
        float z0 = b0, z1 = b1v;
#pragma unroll 8
        for (int k = 0; k < 32; k++) {
            float xk = __shfl_sync(0xffffffffu, xa, k);
            z0 = fmaf(xk, sm[k * 64 + l], z0);
            z1 = fmaf(xk, sm[k * 64 + l + 32], z1);
        }
#pragma unroll 8
        for (int k = 0; k < 32; k++) {
            float xk = __shfl_sync(0xffffffffu, xb, k);
            z0 = fmaf(xk, sm[(k + 32) * 64 + l], z0);
            z1 = fmaf(xk, sm[(k + 32) * 64 + l + 32], z1);
        }
#pragma unroll 8
        for (int k = 0; k < 32; k++) {
            float xk = __shfl_sync(0xffffffffu, xc, k);
            z0 = fmaf(xk, sm[(k + 64) * 64 + l], z0);
            z1 = fmaf(xk, sm[(k + 64) * 64 + l + 32], z1);
        }
        float mu = wsum(z0 + z1) * (1.f / 64.f);
        float sq = wsum(z0 * z0 + z1 * z1) * (1.f / 64.f);
        float rs = rsqrtf(sq - mu * mu + 1e-5f);
        g_xenc[n * 64 + l]      = (z0 - mu) * rs * g0 + bb0;
        g_xenc[n * 64 + l + 32] = (z1 - mu) * rs * g1 + bb1;
    }
}

// ---------------- Pa/Pb precompute: 2 nodes per warp, fp16 output ----------------
__global__ void __launch_bounds__(256) k_prep(
    int use_h, const float* __restrict__ w1, const float* __restrict__ b1)
{
    extern __shared__ float sm[];
    for (int i = threadIdx.x; i < 128 * 128; i += blockDim.x) sm[i] = w1[i];
    __syncthreads();
    const float* xin = use_h ? g_h1 : g_xenc;
    int l = threadIdx.x & 31;
    int warp = (blockIdx.x * blockDim.x + threadIdx.x) >> 5;
    int nwarps = (gridDim.x * blockDim.x) >> 5;
    float4 bv = *(const float4*)(b1 + 4 * l);
    for (int n = warp * 2; n < NN; n += nwarps * 2) {
        float xA0 = xin[n * 64 + l],       xA1 = xin[n * 64 + 32 + l];
        float xB0 = xin[(n + 1) * 64 + l], xB1 = xin[(n + 1) * 64 + 32 + l];
        float4 paA = bv, paB = bv;
        float4 pbA = make_float4(0.f, 0.f, 0.f, 0.f);
        float4 pbB = make_float4(0.f, 0.f, 0.f, 0.f);
#pragma unroll 8
        for (int k = 0; k < 32; k++) {
            float kA = __shfl_sync(0xffffffffu, xA0, k);
            float kB = __shfl_sync(0xffffffffu, xB0, k);
            float4 wa = *(const float4*)(sm + k * 128 + 4 * l);
            float4 wb = *(const float4*)(sm + (k + 64) * 128 + 4 * l);
            paA.x = fmaf(kA, wa.x, paA.x); paA.y = fmaf(kA, wa.y, paA.y);
            paA.z = fmaf(kA, wa.z, paA.z); paA.w = fmaf(kA, wa.w, paA.w);
            pbA.x = fmaf(kA, wb.x, pbA.x); pbA.y = fmaf(kA, wb.y, pbA.y);
            pbA.z = fmaf(kA, wb.z, pbA.z); pbA.w = fmaf(kA, wb.w, pbA.w);
            paB.x = fmaf(kB, wa.x, paB.x); paB.y = fmaf(kB, wa.y, paB.y);
            paB.z = fmaf(kB, wa.z, paB.z); paB.w = fmaf(kB, wa.w, paB.w);
            pbB.x = fmaf(kB, wb.x, pbB.x); pbB.y = fmaf(kB, wb.y, pbB.y);
            pbB.z = fmaf(kB, wb.z, pbB.z); pbB.w = fmaf(kB, wb.w, pbB.w);
        }
#pragma unroll 8
        for (int k = 0; k < 32; k++) {
            float kA = __shfl_sync(0xffffffffu, xA1, k);
            float kB = __shfl_sync(0xffffffffu, xB1, k);
            float4 wa = *(const float4*)(sm + (k + 32) * 128 + 4 * l);
            float4 wb = *(const float4*)(sm + (k + 96) * 128 + 4 * l);
            paA.x = fmaf(kA, wa.x, paA.x); paA.y = fmaf(kA, wa.y, paA.y);
            paA.z = fmaf(kA, wa.z, paA.z); paA.w = fmaf(kA, wa.w, paA.w);
            pbA.x = fmaf(kA, wb.x, pbA.x); pbA.y = fmaf(kA, wb.y, pbA.y);
            pbA.z = fmaf(kA, wb.z, pbA.z); pbA.w = fmaf(kA, wb.w, pbA.w);
            paB.x = fmaf(kB, wa.x, paB.x); paB.y = fmaf(kB, wa.y, paB.y);
            paB.z = fmaf(kB, wa.z, paB.z); paB.w = fmaf(kB, wa.w, paB.w);
            pbB.x = fmaf(kB, wb.x, pbB.x); pbB.y = fmaf(kB, wb.y, pbB.y);
            pbB.z = fmaf(kB, wb.z, pbB.z); pbB.w = fmaf(kB, wb.w, pbB.w);
        }
        uint2 va, vb;
        va.x = packh2(paA.x, paA.y); va.y = packh2(paA.z, paA.w);
        vb.x = packh2(pbA.x, pbA.y); vb.y = packh2(pbA.z, pbA.w);
        *(uint2*)(g_Pa + (size_t)n * 128 + 4 * l) = va;
        *(uint2*)(g_Pb + (size_t)n * 128 + 4 * l) = vb;
        va.x = packh2(paB.x, paB.y); va.y = packh2(paB.z, paB.w);
        vb.x = packh2(pbB.x, pbB.y); vb.y = packh2(pbB.z, pbB.w);
        *(uint2*)(g_Pa + (size_t)(n + 1) * 128 + 4 * l) = va;
        *(uint2*)(g_Pb + (size_t)(n + 1) * 128 + 4 * l) = vb;
    }
}

// ---------------- mma.sync edge kernel: R14 structure, fp16 Pab gathers ----------------
__global__ void __launch_bounds__(256, 2) k_edge(
    int conv, const int* __restrict__ ei, const float* __restrict__ eattr,
    const float* __restrict__ eenc_w, const float* __restrict__ eenc_b,
    const float* __restrict__ ln_g, const float* __restrict__ ln_b,
    const float* __restrict__ w1, const float* __restrict__ w2,
    const float* __restrict__ b2, const float* __restrict__ tptr)
{
    extern __shared__ __align__(1024) char smraw[];
    const u32 sb = smem_u32(smraw);
    int tid = threadIdx.x;
    int wid = tid >> 5, lane = tid & 31;

    u64* seb  = (u64*)(smraw + SO_SEB);
    u64* sgp  = (u64*)(smraw + SO_SGP);
    u64* sbbp = (u64*)(smraw + SO_SBBP);
    u64* eewp = (u64*)(smraw + SO_EEW);
    float* sb2 = (float*)(smraw + SO_SB2);

    // ---- one-time staging: fp16 weights (hi only) ----
    for (int i = tid; i < 64 * 128; i += 256) {        // W1c^T [h][k], stride 144
        int k = i >> 7, h = i & 127;
        *(u16*)(smraw + SO_W1T + h * 144 + k * 2) =
            __half_as_ushort(__float2half_rn(w1[(128 + k) * 128 + h]));
    }
    for (int i = tid; i < 128 * 64; i += 256) {        // W2^T [c][k], stride 272
        int k = i >> 6, c = i & 63;
        *(u16*)(smraw + SO_W2T + c * 272 + k * 2) =
            __half_as_ushort(__float2half_rn(w2[k * 64 + c]));
    }
    if (conv == 0) {
        for (int i = tid; i < 512; i += 256) eewp[i] = ((const u64*)eenc_w)[i];
        if (tid < 32) seb[tid] = ((const u64*)eenc_b)[tid];
    }
    if (tid < 32) {
        sgp[tid]  = ((const u64*)ln_g)[tid];
        sbbp[tid] = ((const u64*)ln_b)[tid];
    }
    if (tid < 64) sb2[tid] = b2[tid];
    __syncthreads();

    const float t = tptr[0];
    const int* srcp = ei;
    const int* dstp = ei + NE;
    float* ndb = conv ? g_nd1 : g_nd0;

    char* pw_c = smraw + SO_WARP + wid * PW_BYTES;
    const u32 pwb   = sb + SO_WARP + wid * PW_BYTES;
    const u32 eah_b = pwb + PO_EAH;
    const u32 hb_b  = pwb + PO_HB;
    float* ndt = (float*)(pw_c + PO_NDT);   // aliases EAH+HB (dead by epilogue2)

    const int el = lane >> 1, half = lane & 1;
    const int r0 = lane >> 2, tp = lane & 3;
    const int hl = ((lane >> 4) << 3) | (lane & 7);
    const int khalf = (lane >> 3) & 1;
    const u32 aoff_ea = (u32)((lane & 15) * 144 + (lane >> 4) * 16);
    const u32 boff4_w1 = (u32)(hl * 144 + khalf * 16);
    const u32 boff4_w2 = (u32)(hl * 272 + khalf * 16);
    const u32 aoff_hb = (u32)((lane & 15) * 48 + (lane >> 4) * 16);

    const int gw = blockIdx.x * NWARPS_E + wid;
    const int nw = gridDim.x * NWARPS_E;
    for (int g = gw; g < NE / 16; g += nw) {
        const int e16 = g * 16;
        // ---------- phase A: edge features + LN -> EA (fp16) ----------
        {
            u64 z[16];
            if (conv == 0) {
                float ar[16];
                const float4* ap = (const float4*)(eattr + (size_t)(e16 + el) * 16);
                *(float4*)&ar[0]  = ap[0]; *(float4*)&ar[4]  = ap[1];
                *(float4*)&ar[8]  = ap[2]; *(float4*)&ar[12] = ap[3];
#pragma unroll
                for (int j = 0; j < 16; j++) z[j] = seb[half * 16 + j];
#pragma unroll
                for (int k = 0; k < 16; k++) {
                    u64 av = pack2(ar[k], ar[k]);
                    const ulonglong2* wr2 = (const ulonglong2*)(eewp + k * 32 + half * 16);
#pragma unroll
                    for (int j = 0; j < 8; j++) {
                        ulonglong2 w = wr2[j];
                        z[2 * j]     = fma2(av, w.x, z[2 * j]);
                        z[2 * j + 1] = fma2(av, w.y, z[2 * j + 1]);
                    }
                }
            } else {
                const u64* mp = (const u64*)(g_msg0 + (size_t)(e16 + el) * 64 + half * 32);
#pragma unroll
                for (int j = 0; j < 16; j++) z[j] = mp[j];
            }
            u64 s2 = 0ull, q2 = 0ull;
#pragma unroll
            for (int j = 0; j < 16; j++) { s2 = add2(s2, z[j]); q2 = fma2(z[j], z[j], q2); }
            float sl, sh2, ql, qh;
            unpack2(s2, sl, sh2); unpack2(q2, ql, qh);
            float ps = sl + sh2, pq = ql + qh;
            ps += __shfl_xor_sync(0xffffffffu, ps, 1);
            pq += __shfl_xor_sync(0xffffffffu, pq, 1);
            float mu = ps * (1.f / 64.f);
            float rs = rsqrtf(pq * (1.f / 64.f) - mu * mu + 1e-5f);
            u64 nmu2 = pack2(-mu, -mu), rs2 = pack2(rs, rs);
#pragma unroll
            for (int j = 0; j < 16; j++) {
                u64 cen = mul2(add2(z[j], nmu2), rs2);
                u64 v = fma2(cen, sgp[half * 16 + j], sbbp[half * 16 + j]);
                float lo, hi; unpack2(v, lo, hi);
                int ch = half * 32 + 2 * j;
                *(u32*)(pw_c + PO_EAH + el * 144 + ch * 2) = packh2(lo, hi);
            }
        }
        // this thread's edge rows (r0 and r0+8)
        const int d0  = dstp[e16 + r0],     s0  = srcp[e16 + r0];
        const int d1v = dstp[e16 + r0 + 8], s1v = srcp[e16 + r0 + 8];
        __syncwarp();
        // ---------- GEMM1: D1[16e][128h] = EA @ W1c^T ----------
        float d1[16][4];
#pragma unroll
        for (int nt = 0; nt < 16; nt++) { d1[nt][0] = d1[nt][1] = d1[nt][2] = d1[nt][3] = 0.f; }
#pragma unroll
        for (int kc = 0; kc < 4; kc++) {
            u32 ah0, ah1, ah2, ah3;
            LDSM4(ah0, ah1, ah2, ah3, eah_b + kc * 32 + aoff_ea);
#pragma unroll
            for (int p = 0; p < 8; p++) {
                u32 bh0, bh1, bh2, bh3;
                LDSM4(bh0, bh1, bh2, bh3,
                      sb + SO_W1T + (u32)(p * 2304 + kc * 32) + boff4_w1);
                MMAH(d1[2 * p],     ah0, ah1, ah2, ah3, bh0, bh1);
                MMAH(d1[2 * p + 1], ah0, ah1, ah2, ah3, bh2, bh3);
            }
        }
        // ---------- fused epilogue1 + GEMM2 (fp16 Pab direct from L2, prefetch 1 hc) ----------
        float d2[8][4];
#pragma unroll
        for (int ct = 0; ct < 8; ct++) { d2[ct][0] = d2[ct][1] = d2[ct][2] = d2[ct][3] = 0.f; }
        u32 pf[8];
        {
            int cb = 2 * tp;
            pf[0] = *(const u32*)(g_Pa + (size_t)d0 * 128 + cb);
            pf[1] = *(const u32*)(g_Pb + (size_t)s0 * 128 + cb);
            pf[2] = *(const u32*)(g_Pa + (size_t)d0 * 128 + cb + 8);
            pf[3] = *(const u32*)(g_Pb + (size_t)s0 * 128 + cb + 8);
            pf[4] = *(const u32*)(g_Pa + (size_t)d1v * 128 + cb);
            pf[5] = *(const u32*)(g_Pb + (size_t)s1v * 128 + cb);
            pf[6] = *(const u32*)(g_Pa + (size_t)d1v * 128 + cb + 8);
            pf[7] = *(const u32*)(g_Pb + (size_t)s1v * 128 + cb + 8);
        }
#pragma unroll
        for (int hc = 0; hc < 8; hc++) {
            u32 nf[8];
            if (hc < 7) {
                int cb = (hc + 1) * 16 + 2 * tp;
                nf[0] = *(const u32*)(g_Pa + (size_t)d0 * 128 + cb);
                nf[1] = *(const u32*)(g_Pb + (size_t)s0 * 128 + cb);
                nf[2] = *(const u32*)(g_Pa + (size_t)d0 * 128 + cb + 8);
                nf[3] = *(const u32*)(g_Pb + (size_t)s0 * 128 + cb + 8);
                nf[4] = *(const u32*)(g_Pa + (size_t)d1v * 128 + cb);
                nf[5] = *(const u32*)(g_Pb + (size_t)s1v * 128 + cb);
                nf[6] = *(const u32*)(g_Pa + (size_t)d1v * 128 + cb + 8);
                nf[7] = *(const u32*)(g_Pb + (size_t)s1v * 128 + cb + 8);
            }
            int n0 = 2 * hc, n1 = 2 * hc + 1;
            u32 slot = (hc & 1) ? 768u : 0u;
#pragma unroll
            for (int rr = 0; rr < 2; rr++) {
                int r = r0 + 8 * rr;
                float2 fa0 = h2f2(pf[4 * rr]),     fb0 = h2f2(pf[4 * rr + 1]);
                float2 fa1 = h2f2(pf[4 * rr + 2]), fb1 = h2f2(pf[4 * rr + 3]);
                float v0 = fmaxf(d1[n0][2 * rr]     + fa0.x + fb0.x, 0.f);
                float v1 = fmaxf(d1[n0][2 * rr + 1] + fa0.y + fb0.y, 0.f);
                float v2 = fmaxf(d1[n1][2 * rr]     + fa1.x + fb1.x, 0.f);
                float v3 = fmaxf(d1[n1][2 * rr + 1] + fa1.y + fb1.y, 0.f);
                char* hrow = pw_c + PO_HB + slot + r * 48;
                *(u32*)(hrow + 4 * tp)      = packh2(v0, v1);
                *(u32*)(hrow + 16 + 4 * tp) = packh2(v2, v3);
            }
            __syncwarp();
            u32 ah0, ah1, ah2, ah3;
            LDSM4(ah0, ah1, ah2, ah3, hb_b + slot + aoff_hb);
#pragma unroll
            for (int q = 0; q < 4; q++) {
                u32 bh0, bh1, bh2, bh3;
                LDSM4(bh0, bh1, bh2, bh3,
                      sb + SO_W2T + (u32)(q * 4352 + hc * 32) + boff4_w2);
                MMAH(d2[2 * q],     ah0, ah1, ah2, ah3, bh0, bh1);
                MMAH(d2[2 * q + 1], ah0, ah1, ah2, ah3, bh2, bh3);
            }
            __syncwarp();
            if (hc < 7) {
#pragma unroll
                for (int j = 0; j < 8; j++) pf[j] = nf[j];
            }
        }
        __syncwarp();   // HB/EAH dead; ndt (aliased) safe to write
        // ---------- epilogue2: + b2, exp -> smem transpose -> coalesced RED ----------
#pragma unroll
        for (int rr = 0; rr < 2; rr++) {
            int r = r0 + 8 * rr;
            int e = e16 + r;
#pragma unroll
            for (int ct = 0; ct < 8; ct++) {
                int c0 = 8 * ct + 2 * tp;
                float m0 = d2[ct][2 * rr]     + sb2[c0];
                float m1 = d2[ct][2 * rr + 1] + sb2[c0 + 1];
                float E0 = __expf(m0 * t), E1 = __expf(m1 * t);
                *(float4*)(ndt + r0 * 136 + 2 * c0) = make_float4(m0 * E0, E0, m1 * E1, E1);
                if (conv == 0)
                    *(float2*)(g_msg0 + (size_t)e * 64 + c0) = make_float2(m0, m1);
            }
            __syncwarp();
#pragma unroll 4
            for (int eb = 0; eb < 8; eb++) {
                int d = dstp[e16 + 8 * rr + eb];        // warp-uniform broadcast
                float4 v = *(const float4*)(ndt + eb * 136 + 4 * lane);
                asm volatile("red.global.add.v4.f32 [%0], {%1,%2,%3,%4};"
                             :: "l"(ndb + (size_t)d * 128 + 4 * lane),
                                "f"(v.x), "f"(v.y), "f"(v.z), "f"(v.w) : "memory");
            }
            __syncwarp();
        }
    }
}

// ---------------- conv0 node finish ----------------
__global__ void __launch_bounds__(256) k_node0(
    const float* __restrict__ wr, const float* __restrict__ lg, const float* __restrict__ lb)
{
    extern __shared__ float sm[];
    for (int i = threadIdx.x; i < 64 * 64; i += blockDim.x) sm[i] = wr[i];
    __syncthreads();
    int l = threadIdx.x & 31;
    int warp = (blockIdx.x * blockDim.x + threadIdx.x) >> 5;
    int nwarps = (gridDim.x * blockDim.x) >> 5;
    float g0 = lg[l], g1 = lg[l + 32], b0 = lb[l], b1v = lb[l + 32];
    for (int n = warp; n < NN; n += nwarps) {
        float xe0 = g_xenc[n * 64 + l], xe1 = g_xenc[n * 64 + 32 + l];
        float r0 = 0.f, r1 = 0.f;
#pragma unroll 8
        for (int k = 0; k < 32; k++) {
            float xk = __shfl_sync(0xffffffffu, xe0, k);
            r0 = fmaf(xk, sm[k * 64 + l], r0);
            r1 = fmaf(xk, sm[k * 64 + l + 32], r1);
        }
#pragma unroll 8
        for (int k = 0; k < 32; k++) {
            float xk = __shfl_sync(0xffffffffu, xe1, k);
            r0 = fmaf(xk, sm[(k + 32) * 64 + l], r0);
            r1 = fmaf(xk, sm[(k + 32) * 64 + l + 32], r1);
        }
        float2 na = *(const float2*)(g_nd0 + (size_t)n * 128 + 2 * l);
        float2 nb = *(const float2*)(g_nd0 + (size_t)n * 128 + 64 + 2 * l);
        float x10 = ((na.y != 0.f) ? na.x / na.y : 0.f) + r0;
        float x11 = ((nb.y != 0.f) ? nb.x / nb.y : 0.f) + r1;
        g_x1[n * 64 + l] = x10;
        g_x1[n * 64 + l + 32] = x11;
        float mu = wsum(x10 + x11) * (1.f / 64.f);
        float sq = wsum(x10 * x10 + x11 * x11) * (1.f / 64.f);
        float rs = rsqrtf(sq - mu * mu + 1e-5f);
        g_h1[n * 64 + l]      = fmaxf((x10 - mu) * rs * g0 + b0, 0.f);
        g_h1[n * 64 + l + 32] = fmaxf((x11 - mu) * rs * g1 + b1v, 0.f);
    }
}

// ---------------- final node kernel ----------------
__global__ void __launch_bounds__(256) k_node1(
    const float* __restrict__ wr, float* __restrict__ out)
{
    extern __shared__ float sm[];
    for (int i = threadIdx.x; i < 64 * 64; i += blockDim.x) sm[i] = wr[i];
    __syncthreads();
    int l = threadIdx.x & 31;
    int warp = (blockIdx.x * blockDim.x + threadIdx.x) >> 5;
    int nwarps = (gridDim.x * blockDim.x) >> 5;
    for (int n = warp; n < NN; n += nwarps) {
        float he0 = g_h1[n * 64 + l], he1 = g_h1[n * 64 + 32 + l];
        float r0 = 0.f, r1 = 0.f;
#pragma unroll 8
        for (int k = 0; k < 32; k++) {
            float xk = __shfl_sync(0xffffffffu, he0, k);
            r0 = fmaf(xk, sm[k * 64 + l], r0);
            r1 = fmaf(xk, sm[k * 64 + l + 32], r1);
        }
#pragma unroll 8
        for (int k = 0; k < 32; k++) {
            float xk = __shfl_sync(0xffffffffu, he1, k);
            r0 = fmaf(xk, sm[(k + 32) * 64 + l], r0);
            r1 = fmaf(xk, sm[(k + 32) * 64 + l + 32], r1);
        }
        float2 na = *(const float2*)(g_nd1 + (size_t)n * 128 + 2 * l);
        float2 nb = *(const float2*)(g_nd1 + (size_t)n * 128 + 64 + 2 * l);
        float a0 = ((na.y != 0.f) ? na.x / na.y : 0.f) + r0;
        float a1 = ((nb.y != 0.f) ? nb.x / nb.y : 0.f) + r1;
        out[n * 64 + l]      = g_x1[n * 64 + l] + a0;
        out[n * 64 + l + 32] = g_x1[n * 64 + l + 32] + a1;
    }
}

extern "C" void kernel_launch(void* const* d_in, const int* in_sizes, int n_in,
                              void* d_out, int out_size)
{
    const float* x       = (const float*)d_in[0];
    const int*   ei      = (const int*)  d_in[1];
    const float* eattr   = (const float*)d_in[2];
    const float* enc_w   = (const float*)d_in[3];
    const float* enc_b   = (const float*)d_in[4];
    const float* enc_g   = (const float*)d_in[5];
    const float* enc_bb  = (const float*)d_in[6];
    const float* eenc_w  = (const float*)d_in[7];
    const float* eenc_b  = (const float*)d_in[8];
    const float* eenc_g  = (const float*)d_in[9];
    const float* eenc_bb = (const float*)d_in[10];
    const float* c0_w1   = (const float*)d_in[11];
    const float* c0_b1   = (const float*)d_in[12];
    const float* c0_w2   = (const float*)d_in[13];
    const float* c0_b2   = (const float*)d_in[14];
    const float* c0_wr   = (const float*)d_in[15];
    const float* c0_t    = (const float*)d_in[16];
    const float* l1_g    = (const float*)d_in[17];
    const float* l1_b    = (const float*)d_in[18];
    const float* l1_eg   = (const float*)d_in[19];
    const float* l1_eb   = (const float*)d_in[20];
    const float* c1_w1   = (const float*)d_in[21];
    const float* c1_b1   = (const float*)d_in[22];
    const float* c1_w2   = (const float*)d_in[23];
    const float* c1_b2   = (const float*)d_in[24];
    const float* c1_wr   = (const float*)d_in[25];
    const float* c1_t    = (const float*)d_in[26];
    float* out = (float*)d_out;

    cudaFuncSetAttribute(k_prep, cudaFuncAttributeMaxDynamicSharedMemorySize, 65536);
    cudaFuncSetAttribute(k_edge, cudaFuncAttributeMaxDynamicSharedMemorySize, SM_EDGE_BYTES);

    k_zero<<<2500, 256>>>();
    k_encode<<<320, 256, 24576>>>(x, enc_w, enc_b, enc_g, enc_bb);
    k_prep<<<444, 256, 65536>>>(0, c0_w1, c0_b1);
    k_edge<<<296, 256, SM_EDGE_BYTES>>>(0, ei, eattr, eenc_w, eenc_b, eenc_g, eenc_bb,
                                        c0_w1, c0_w2, c0_b2, c0_t);
    k_node0<<<320, 256, 16384>>>(c0_wr, l1_g, l1_b);
    k_prep<<<444, 256, 65536>>>(1, c1_w1, c1_b1);
    k_edge<<<296, 256, SM_EDGE_BYTES>>>(1, ei, eattr, eenc_w, eenc_b, l1_eg, l1_eb,
                                        c1_w1, c1_w2, c1_b2, c1_t);
    k_node1<<<320, 256, 16384>>>(c1_wr, out);
}

// round 16
// speedup vs baseline: 1.0862x; 1.0862x over previous
#include <cuda_runtime.h>
#include <cuda_fp16.h>
#include <math.h>

#define NN 20000
#define NE 640000

typedef unsigned long long u64;
typedef unsigned int u32;
typedef unsigned short u16;

// ---------------- scratch (device globals) ----------------
__device__ __align__(16) float g_xenc[NN * 64];
__device__ __align__(16) float g_x1[NN * 64];
__device__ __align__(16) float g_h1[NN * 64];
__device__ __align__(16) __half g_x16[NN * 64];   // fp16 node features for edge GEMM
__device__ __align__(16) float g_nd0[NN * 128];
__device__ __align__(16) float g_nd1[NN * 128];
__device__ __align__(16) float g_msg0[(size_t)NE * 64];

// ---------------- f32x2 helpers ----------------
static __device__ __forceinline__ u64 fma2(u64 a, u64 b, u64 c) {
    u64 d; asm("fma.rn.f32x2 %0,%1,%2,%3;" : "=l"(d) : "l"(a), "l"(b), "l"(c)); return d;
}
static __device__ __forceinline__ u64 add2(u64 a, u64 b) {
    u64 d; asm("add.rn.f32x2 %0,%1,%2;" : "=l"(d) : "l"(a), "l"(b)); return d;
}
static __device__ __forceinline__ u64 mul2(u64 a, u64 b) {
    u64 d; asm("mul.rn.f32x2 %0,%1,%2;" : "=l"(d) : "l"(a), "l"(b)); return d;
}
static __device__ __forceinline__ u64 pack2(float lo, float hi) {
    u64 d; asm("mov.b64 %0,{%1,%2};" : "=l"(d) : "f"(lo), "f"(hi)); return d;
}
static __device__ __forceinline__ void unpack2(u64 a, float& lo, float& hi) {
    asm("mov.b64 {%0,%1},%2;" : "=f"(lo), "=f"(hi) : "l"(a));
}
static __device__ __forceinline__ float wsum(float v) {
#pragma unroll
    for (int o = 16; o; o >>= 1) v += __shfl_xor_sync(0xffffffffu, v, o);
    return v;
}
static __device__ __forceinline__ u32 smem_u32(const void* p) {
    u32 a; asm("{ .reg .u64 t; cvta.to.shared.u64 t, %1; cvt.u32.u64 %0, t; }" : "=r"(a) : "l"(p));
    return a;
}
static __device__ __forceinline__ u32 packh2(float x, float y) {
    __half hx = __float2half_rn(x), hy = __float2half_rn(y);
    return (u32)__half_as_ushort(hx) | ((u32)__half_as_ushort(hy) << 16);
}

#define LDSM4(r0, r1, r2, r3, a)                                             \
    asm volatile("ldmatrix.sync.aligned.m8n8.x4.shared.b16 {%0,%1,%2,%3}, [%4];" \
                 : "=r"(r0), "=r"(r1), "=r"(r2), "=r"(r3) : "r"(a))
#define MMAH(d, a0, a1, a2, a3, b0, b1)                                      \
    asm volatile("mma.sync.aligned.m16n8k16.row.col.f32.f16.f16.f32 "        \
                 "{%0,%1,%2,%3}, {%4,%5,%6,%7}, {%8,%9}, {%0,%1,%2,%3};"     \
                 : "+f"((d)[0]), "+f"((d)[1]), "+f"((d)[2]), "+f"((d)[3])    \
                 : "r"(a0), "r"(a1), "r"(a2), "r"(a3), "r"(b0), "r"(b1))

// ---------------- k_edge smem layout (bytes) ----------------
#define SO_W1T   0         // [128h][192k] fp16, stride 400 (51200), k-order [ea|dst|src]
#define SO_W2T   51200     // [64c][128k] fp16, stride 272  (17408)
#define SO_SB1   68608     // float[128]
#define SO_SB2   69120     // float[64]
#define SO_SEB   69376     // u64[32]
#define SO_SGP   69632
#define SO_SBBP  69888
#define SO_EEW   70144     // u64[512]
#define SO_WARP  74240     // per-warp regions
#define PW_BYTES 7936
#define PO_A     0         // [16e][192k] fp16, stride 400 (6400); ndt aliases (4352)
#define PO_HB    6400      // 2 slots x 768
#define NWARPS_E 12
#define SM_EDGE_BYTES (74240 + NWARPS_E * PW_BYTES)   // 169472

// ---------------- zero accumulators ----------------
__global__ void k_zero() {
    int i = blockIdx.x * blockDim.x + threadIdx.x;
    if (i < NN * 128 / 4) {
        float4 z = make_float4(0.f, 0.f, 0.f, 0.f);
        ((float4*)g_nd0)[i] = z;
        ((float4*)g_nd1)[i] = z;
    }
}

// ---------------- node encoder (also writes fp16 features) ----------------
__global__ void __launch_bounds__(256) k_encode(
    const float* __restrict__ x, const float* __restrict__ enc_w,
    const float* __restrict__ enc_b, const float* __restrict__ enc_g,
    const float* __restrict__ enc_bb)
{
    extern __shared__ float sm[];
    for (int i = threadIdx.x; i < 96 * 64; i += blockDim.x) sm[i] = enc_w[i];
    __syncthreads();
    int l = threadIdx.x & 31;
    int warp = (blockIdx.x * blockDim.x + threadIdx.x) >> 5;
    int nwarps = (gridDim.x * blockDim.x) >> 5;
    float b0 = enc_b[l], b1v = enc_b[l + 32];
    float g0 = enc_g[l], g1 = enc_g[l + 32];
    float bb0 = enc_bb[l], bb1 = enc_bb[l + 32];
    for (int n = warp; n < NN; n += nwarps) {
        float xa = x[(size_t)n * 96 + l];
        float xb = x[(size_t)n * 96 + 32 + l];
        float xc = x[(size_t)n * 96 + 64 + l];
        float z0 = b0, z1 = b1v;
#pragma unroll 8
        for (int k = 0; k < 32; k++) {
            float xk = __shfl_sync(0xffffffffu, xa, k);
            z0 = fmaf(xk, sm[k * 64 + l], z0);
            z1 = fmaf(xk, sm[k * 64 + l + 32], z1);
        }
#pragma unroll 8
        for (int k = 0; k < 32; k++) {
            float xk = __shfl_sync(0xffffffffu, xb, k);
            z0 = fmaf(xk, sm[(k + 32) * 64 + l], z0);
            z1 = fmaf(xk, sm[(k + 32) * 64 + l + 32], z1);
        }
#pragma unroll 8
        for (int k = 0; k < 32; k++) {
            float xk = __shfl_sync(0xffffffffu, xc, k);
            z0 = fmaf(xk, sm[(k + 64) * 64 + l], z0);
            z1 = fmaf(xk, sm[(k + 64) * 64 + l + 32], z1);
        }
        float mu = wsum(z0 + z1) * (1.f / 64.f);
        float sq = wsum(z0 * z0 + z1 * z1) * (1.f / 64.f);
        float rs = rsqrtf(sq - mu * mu + 1e-5f);
        float xe0 = (z0 - mu) * rs * g0 + bb0;
        float xe1 = (z1 - mu) * rs * g1 + bb1;
        g_xenc[n * 64 + l]      = xe0;
        g_xenc[n * 64 + l + 32] = xe1;
        g_x16[n * 64 + l]      = __float2half_rn(xe0);
        g_x16[n * 64 + l + 32] = __float2half_rn(xe1);
    }
}

// ---------------- mma.sync edge kernel: K=192 fused node+edge GEMM ----------------
__global__ void __launch_bounds__(384) k_edge(
    int conv, const int* __restrict__ ei, const float* __restrict__ eattr,
    const float* __restrict__ eenc_w, const float* __restrict__ eenc_b,
    const float* __restrict__ ln_g, const float* __restrict__ ln_b,
    const float* __restrict__ w1, const float* __restrict__ b1,
    const float* __restrict__ w2, const float* __restrict__ b2,
    const float* __restrict__ tptr)
{
    extern __shared__ __align__(1024) char smraw[];
    const u32 sb = smem_u32(smraw);
    int tid = threadIdx.x;
    int wid = tid >> 5, lane = tid & 31;

    u64* seb  = (u64*)(smraw + SO_SEB);
    u64* sgp  = (u64*)(smraw + SO_SGP);
    u64* sbbp = (u64*)(smraw + SO_SBBP);
    u64* eewp = (u64*)(smraw + SO_EEW);
    float* sb1 = (float*)(smraw + SO_SB1);
    float* sb2 = (float*)(smraw + SO_SB2);

    // ---- one-time staging: fp16 weights; W1^T k-order = [ea | dst | src] ----
    for (int i = tid; i < 128 * 192; i += 384) {       // i = k*128 + h
        int k = i >> 7, h = i & 127;
        int srow = (k < 64) ? (128 + k) : (k - 64);    // ea rows 128..191; dst 0..63; src 64..127
        *(u16*)(smraw + SO_W1T + h * 400 + k * 2) =
            __half_as_ushort(__float2half_rn(w1[srow * 128 + h]));
    }
    for (int i = tid; i < 128 * 64; i += 384) {        // W2^T [c][k], stride 272
        int k = i >> 6, c = i & 63;
        *(u16*)(smraw + SO_W2T + c * 272 + k * 2) =
            __half_as_ushort(__float2half_rn(w2[k * 64 + c]));
    }
    if (conv == 0) {
        for (int i = tid; i < 512; i += 384) eewp[i] = ((const u64*)eenc_w)[i];
        if (tid < 32) seb[tid] = ((const u64*)eenc_b)[tid];
    }
    if (tid < 32) {
        sgp[tid]  = ((const u64*)ln_g)[tid];
        sbbp[tid] = ((const u64*)ln_b)[tid];
    }
    if (tid < 128) sb1[tid] = b1[tid];
    if (tid < 64)  sb2[tid] = b2[tid];
    __syncthreads();

    const float t = tptr[0];
    const int* srcp = ei;
    const int* dstp = ei + NE;
    float* ndb = conv ? g_nd1 : g_nd0;
    const char* x16c = (const char*)g_x16;

    char* pw_c = smraw + SO_WARP + wid * PW_BYTES;
    const u32 pwb  = sb + SO_WARP + wid * PW_BYTES;
    const u32 a_b  = pwb + PO_A;
    const u32 hb_b = pwb + PO_HB;
    float* ndt = (float*)(pw_c + PO_A);   // aliases A tile (dead after GEMM1)

    const int el = lane >> 1, half = lane & 1;
    const int r0 = lane >> 2, tp = lane & 3;
    const int hl = ((lane >> 4) << 3) | (lane & 7);
    const int khalf = (lane >> 3) & 1;
    const u32 aoff_a = (u32)((lane & 15) * 400 + (lane >> 4) * 16);
    const u32 boff4_w1 = (u32)(hl * 400 + khalf * 16);
    const u32 boff4_w2 = (u32)(hl * 272 + khalf * 16);
    const u32 aoff_hb = (u32)((lane & 15) * 48 + (lane >> 4) * 16);

    const int gw = blockIdx.x * NWARPS_E + wid;
    const int nw = gridDim.x * NWARPS_E;
    for (int g = gw; g < NE / 16; g += nw) {
        const int e16 = g * 16;
        // ---------- phase A: edge features + LN -> A[k 0..63] (fp16) ----------
        {
            u64 z[16];
            if (conv == 0) {
                float ar[16];
                const float4* ap = (const float4*)(eattr + (size_t)(e16 + el) * 16);
                *(float4*)&ar[0]  = ap[0]; *(float4*)&ar[4]  = ap[1];
                *(float4*)&ar[8]  = ap[2]; *(float4*)&ar[12] = ap[3];
#pragma unroll
                for (int j = 0; j < 16; j++) z[j] = seb[half * 16 + j];
#pragma unroll
                for (int k = 0; k < 16; k++) {
                    u64 av = pack2(ar[k], ar[k]);
                    const ulonglong2* wr2 = (const ulonglong2*)(eewp + k * 32 + half * 16);
#pragma unroll
                    for (int j = 0; j < 8; j++) {
                        ulonglong2 w = wr2[j];
                        z[2 * j]     = fma2(av, w.x, z[2 * j]);
                        z[2 * j + 1] = fma2(av, w.y, z[2 * j + 1]);
                    }
                }
            } else {
                const u64* mp = (const u64*)(g_msg0 + (size_t)(e16 + el) * 64 + half * 32);
#pragma unroll
                for (int j = 0; j < 16; j++) z[j] = mp[j];
            }
            u64 s2 = 0ull, q2 = 0ull;
#pragma unroll
            for (int j = 0; j < 16; j++) { s2 = add2(s2, z[j]); q2 = fma2(z[j], z[j], q2); }
            float sl, sh2, ql, qh;
            unpack2(s2, sl, sh2); unpack2(q2, ql, qh);
            float ps = sl + sh2, pq = ql + qh;
            ps += __shfl_xor_sync(0xffffffffu, ps, 1);
            pq += __shfl_xor_sync(0xffffffffu, pq, 1);
            float mu = ps * (1.f / 64.f);
            float rs = rsqrtf(pq * (1.f / 64.f) - mu * mu + 1e-5f);
            u64 nmu2 = pack2(-mu, -mu), rs2 = pack2(rs, rs);
#pragma unroll
            for (int j = 0; j < 16; j++) {
                u64 cen = mul2(add2(z[j], nmu2), rs2);
                u64 v = fma2(cen, sgp[half * 16 + j], sbbp[half * 16 + j]);
                float lo, hi; unpack2(v, lo, hi);
                int ch = half * 32 + 2 * j;
                *(u32*)(pw_c + PO_A + el * 400 + ch * 2) = packh2(lo, hi);
            }
        }
        // ---------- x-gather: coalesced fp16 rows into A[k 64..191] ----------
#pragma unroll 4
        for (int r = 0; r < 16; r++) {
            int d = dstp[e16 + r], s = srcp[e16 + r];   // warp-uniform
            u32 vd = *(const u32*)(x16c + (size_t)d * 128 + 4 * lane);
            u32 vs = *(const u32*)(x16c + (size_t)s * 128 + 4 * lane);
            *(u32*)(pw_c + PO_A + r * 400 + 128 + 4 * lane) = vd;
            *(u32*)(pw_c + PO_A + r * 400 + 256 + 4 * lane) = vs;
        }
        __syncwarp();
        // ---------- GEMM1: D1[16e][128h] = A[16e][192k] @ W1^T ----------
        float d1[16][4];
#pragma unroll
        for (int nt = 0; nt < 16; nt++) { d1[nt][0] = d1[nt][1] = d1[nt][2] = d1[nt][3] = 0.f; }
#pragma unroll
        for (int kc = 0; kc < 12; kc++) {
            u32 ah0, ah1, ah2, ah3;
            LDSM4(ah0, ah1, ah2, ah3, a_b + kc * 32 + aoff_a);
#pragma unroll
            for (int p = 0; p < 8; p++) {
                u32 bh0, bh1, bh2, bh3;
                LDSM4(bh0, bh1, bh2, bh3,
                      sb + SO_W1T + (u32)(p * 6400 + kc * 32) + boff4_w1);
                MMAH(d1[2 * p],     ah0, ah1, ah2, ah3, bh0, bh1);
                MMAH(d1[2 * p + 1], ah0, ah1, ah2, ah3, bh2, bh3);
            }
        }
        __syncwarp();
        // ---------- fused epilogue1 (+b1, relu) + GEMM2 ----------
        float d2[8][4];
#pragma unroll
        for (int ct = 0; ct < 8; ct++) { d2[ct][0] = d2[ct][1] = d2[ct][2] = d2[ct][3] = 0.f; }
#pragma unroll
        for (int hc = 0; hc < 8; hc++) {
            int n0 = 2 * hc, n1 = 2 * hc + 1;
            u32 slot = (hc & 1) ? 768u : 0u;
            float2 bA = *(const float2*)(sb1 + hc * 16 + 2 * tp);
            float2 bB = *(const float2*)(sb1 + hc * 16 + 8 + 2 * tp);
#pragma unroll
            for (int rr = 0; rr < 2; rr++) {
                int r = r0 + 8 * rr;
                float v0 = fmaxf(d1[n0][2 * rr]     + bA.x, 0.f);
                float v1 = fmaxf(d1[n0][2 * rr + 1] + bA.y, 0.f);
                float v2 = fmaxf(d1[n1][2 * rr]     + bB.x, 0.f);
                float v3 = fmaxf(d1[n1][2 * rr + 1] + bB.y, 0.f);
                char* hrow = pw_c + PO_HB + slot + r * 48;
                *(u32*)(hrow + 4 * tp)      = packh2(v0, v1);
                *(u32*)(hrow + 16 + 4 * tp) = packh2(v2, v3);
            }
            __syncwarp();
            u32 ah0, ah1, ah2, ah3;
            LDSM4(ah0, ah1, ah2, ah3, hb_b + slot + aoff_hb);
#pragma unroll
            for (int q = 0; q < 4; q++) {
                u32 bh0, bh1, bh2, bh3;
                LDSM4(bh0, bh1, bh2, bh3,
                      sb + SO_W2T + (u32)(q * 4352 + hc * 32) + boff4_w2);
                MMAH(d2[2 * q],     ah0, ah1, ah2, ah3, bh0, bh1);
                MMAH(d2[2 * q + 1], ah0, ah1, ah2, ah3, bh2, bh3);
            }
            __syncwarp();
        }
        __syncwarp();   // A dead; ndt (aliased) safe to write
        // ---------- epilogue2: + b2, exp -> smem transpose -> coalesced RED ----------
#pragma unroll
        for (int rr = 0; rr < 2; rr++) {
            int r = r0 + 8 * rr;
            int e = e16 + r;
#pragma unroll
            for (int ct = 0; ct < 8; ct++) {
                int c0 = 8 * ct + 2 * tp;
                float m0 = d2[ct][2 * rr]     + sb2[c0];
                float m1 = d2[ct][2 * rr + 1] + sb2[c0 + 1];
                float E0 = __expf(m0 * t), E1 = __expf(m1 * t);
                *(float4*)(ndt + r0 * 136 + 2 * c0) = make_float4(m0 * E0, E0, m1 * E1, E1);
                if (conv == 0)
                    *(float2*)(g_msg0 + (size_t)e * 64 + c0) = make_float2(m0, m1);
            }
            __syncwarp();
#pragma unroll 4
            for (int eb = 0; eb < 8; eb++) {
                int d = dstp[e16 + 8 * rr + eb];        // warp-uniform broadcast
                float4 v = *(const float4*)(ndt + eb * 136 + 4 * lane);
                asm volatile("red.global.add.v4.f32 [%0], {%1,%2,%3,%4};"
                             :: "l"(ndb + (size_t)d * 128 + 4 * lane),
                                "f"(v.x), "f"(v.y), "f"(v.z), "f"(v.w) : "memory");
            }
            __syncwarp();
        }
    }
}

// ---------------- conv0 node finish (also writes fp16 h) ----------------
__global__ void __launch_bounds__(256) k_node0(
    const float* __restrict__ wr, const float* __restrict__ lg, const float* __restrict__ lb)
{
    extern __shared__ float sm[];
    for (int i = threadIdx.x; i < 64 * 64; i += blockDim.x) sm[i] = wr[i];
    __syncthreads();
    int l = threadIdx.x & 31;
    int warp = (blockIdx.x * blockDim.x + threadIdx.x) >> 5;
    int nwarps = (gridDim.x * blockDim.x) >> 5;
    float g0 = lg[l], g1 = lg[l + 32], b0 = lb[l], b1v = lb[l + 32];
    for (int n = warp; n < NN; n += nwarps) {
        float xe0 = g_xenc[n * 64 + l], xe1 = g_xenc[n * 64 + 32 + l];
        float r0 = 0.f, r1 = 0.f;
#pragma unroll 8
        for (int k = 0; k < 32; k++) {
            float xk = __shfl_sync(0xffffffffu, xe0, k);
            r0 = fmaf(xk, sm[k * 64 + l], r0);
            r1 = fmaf(xk, sm[k * 64 + l + 32], r1);
        }
#pragma unroll 8
        for (int k = 0; k < 32; k++) {
            float xk = __shfl_sync(0xffffffffu, xe1, k);
            r0 = fmaf(xk, sm[(k + 32) * 64 + l], r0);
            r1 = fmaf(xk, sm[(k + 32) * 64 + l + 32], r1);
        }
        float2 na = *(const float2*)(g_nd0 + (size_t)n * 128 + 2 * l);
        float2 nb = *(const float2*)(g_nd0 + (size_t)n * 128 + 64 + 2 * l);
        float x10 = ((na.y != 0.f) ? na.x / na.y : 0.f) + r0;
        float x11 = ((nb.y != 0.f) ? nb.x / nb.y : 0.f) + r1;
        g_x1[n * 64 + l] = x10;
        g_x1[n * 64 + l + 32] = x11;
        float mu = wsum(x10 + x11) * (1.f / 64.f);
        float sq = wsum(x10 * x10 + x11 * x11) * (1.f / 64.f);
        float rs = rsqrtf(sq - mu * mu + 1e-5f);
        float h0 = fmaxf((x10 - mu) * rs * g0 + b0, 0.f);
        float h1 = fmaxf((x11 - mu) * rs * g1 + b1v, 0.f);
        g_h1[n * 64 + l]      = h0;
        g_h1[n * 64 + l + 32] = h1;
        g_x16[n * 64 + l]      = __float2half_rn(h0);
        g_x16[n * 64 + l + 32] = __float2half_rn(h1);
    }
}

// ---------------- final node kernel ----------------
__global__ void __launch_bounds__(256) k_node1(
    const float* __restrict__ wr, float* __restrict__ out)
{
    extern __shared__ float sm[];
    for (int i = threadIdx.x; i < 64 * 64; i += blockDim.x) sm[i] = wr[i];
    __syncthreads();
    int l = threadIdx.x & 31;
    int warp = (blockIdx.x * blockDim.x + threadIdx.x) >> 5;
    int nwarps = (gridDim.x * blockDim.x) >> 5;
    for (int n = warp; n < NN; n += nwarps) {
        float he0 = g_h1[n * 64 + l], he1 = g_h1[n * 64 + 32 + l];
        float r0 = 0.f, r1 = 0.f;
#pragma unroll 8
        for (int k = 0; k < 32; k++) {
            float xk = __shfl_sync(0xffffffffu, he0, k);
            r0 = fmaf(xk, sm[k * 64 + l], r0);
            r1 = fmaf(xk, sm[k * 64 + l + 32], r1);
        }
#pragma unroll 8
        for (int k = 0; k < 32; k++) {
            float xk = __shfl_sync(0xffffffffu, he1, k);
            r0 = fmaf(xk, sm[(k + 32) * 64 + l], r0);
            r1 = fmaf(xk, sm[(k + 32) * 64 + l + 32], r1);
        }
        float2 na = *(const float2*)(g_nd1 + (size_t)n * 128 + 2 * l);
        float2 nb = *(const float2*)(g_nd1 + (size_t)n * 128 + 64 + 2 * l);
        float a0 = ((na.y != 0.f) ? na.x / na.y : 0.f) + r0;
        float a1 = ((nb.y != 0.f) ? nb.x / nb.y : 0.f) + r1;
        out[n * 64 + l]      = g_x1[n * 64 + l] + a0;
        out[n * 64 + l + 32] = g_x1[n * 64 + l + 32] + a1;
    }
}

extern "C" void kernel_launch(void* const* d_in, const int* in_sizes, int n_in,
                              void* d_out, int out_size)
{
    const float* x       = (const float*)d_in[0];
    const int*   ei      = (const int*)  d_in[1];
    const float* eattr   = (const float*)d_in[2];
    const float* enc_w   = (const float*)d_in[3];
    const float* enc_b   = (const float*)d_in[4];
    const float* enc_g   = (const float*)d_in[5];
    const float* enc_bb  = (const float*)d_in[6];
    const float* eenc_w  = (const float*)d_in[7];
    const float* eenc_b  = (const float*)d_in[8];
    const float* eenc_g  = (const float*)d_in[9];
    const float* eenc_bb = (const float*)d_in[10];
    const float* c0_w1   = (const float*)d_in[11];
    const float* c0_b1   = (const float*)d_in[12];
    const float* c0_w2   = (const float*)d_in[13];
    const float* c0_b2   = (const float*)d_in[14];
    const float* c0_wr   = (const float*)d_in[15];
    const float* c0_t    = (const float*)d_in[16];
    const float* l1_g    = (const float*)d_in[17];
    const float* l1_b    = (const float*)d_in[18];
    const float* l1_eg   = (const float*)d_in[19];
    const float* l1_eb   = (const float*)d_in[20];
    const float* c1_w1   = (const float*)d_in[21];
    const float* c1_b1   = (const float*)d_in[22];
    const float* c1_w2   = (const float*)d_in[23];
    const float* c1_b2   = (const float*)d_in[24];
    const float* c1_wr   = (const float*)d_in[25];
    const float* c1_t    = (const float*)d_in[26];
    float* out = (float*)d_out;

    cudaFuncSetAttribute(k_edge, cudaFuncAttributeMaxDynamicSharedMemorySize, SM_EDGE_BYTES);

    k_zero<<<2500, 256>>>();
    k_encode<<<320, 256, 24576>>>(x, enc_w, enc_b, enc_g, enc_bb);
    k_edge<<<148, 384, SM_EDGE_BYTES>>>(0, ei, eattr, eenc_w, eenc_b, eenc_g, eenc_bb,
                                        c0_w1, c0_b1, c0_w2, c0_b2, c0_t);
    k_node0<<<320, 256, 16384>>>(c0_wr, l1_g, l1_b);
    k_edge<<<148, 384, SM_EDGE_BYTES>>>(1, ei, eattr, eenc_w, eenc_b, l1_eg, l1_eb,
                                        c1_w1, c1_b1, c1_w2, c1_b2, c1_t);
    k_node1<<<320, 256, 16384>>>(c1_wr, out);
}

// round 17
// speedup vs baseline: 1.1172x; 1.0285x over previous
#include <cuda_runtime.h>
#include <cuda_fp16.h>
#include <math.h>

#define NN 20000
#define NE 640000

typedef unsigned long long u64;
typedef unsigned int u32;
typedef unsigned short u16;

// ---------------- scratch (device globals) ----------------
__device__ __align__(16) float g_xenc[NN * 64];
__device__ __align__(16) float g_x1[NN * 64];
__device__ __align__(16) float g_h1[NN * 64];
__device__ __align__(16) __half g_x16[NN * 64];          // fp16 node features
__device__ __align__(16) float g_nd0[NN * 128];
__device__ __align__(16) float g_nd1[NN * 128];
__device__ __align__(16) __half g_msg16[(size_t)NE * 64]; // fp16 LN(msg) for conv1

// ---------------- f32x2 helpers ----------------
static __device__ __forceinline__ u64 fma2(u64 a, u64 b, u64 c) {
    u64 d; asm("fma.rn.f32x2 %0,%1,%2,%3;" : "=l"(d) : "l"(a), "l"(b), "l"(c)); return d;
}
static __device__ __forceinline__ u64 add2(u64 a, u64 b) {
    u64 d; asm("add.rn.f32x2 %0,%1,%2;" : "=l"(d) : "l"(a), "l"(b)); return d;
}
static __device__ __forceinline__ u64 mul2(u64 a, u64 b) {
    u64 d; asm("mul.rn.f32x2 %0,%1,%2;" : "=l"(d) : "l"(a), "l"(b)); return d;
}
static __device__ __forceinline__ u64 pack2(float lo, float hi) {
    u64 d; asm("mov.b64 %0,{%1,%2};" : "=l"(d) : "f"(lo), "f"(hi)); return d;
}
static __device__ __forceinline__ void unpack2(u64 a, float& lo, float& hi) {
    asm("mov.b64 {%0,%1},%2;" : "=f"(lo), "=f"(hi) : "l"(a));
}
static __device__ __forceinline__ float wsum(float v) {
#pragma unroll
    for (int o = 16; o; o >>= 1) v += __shfl_xor_sync(0xffffffffu, v, o);
    return v;
}
static __device__ __forceinline__ u32 smem_u32(const void* p) {
    u32 a; asm("{ .reg .u64 t; cvta.to.shared.u64 t, %1; cvt.u32.u64 %0, t; }" : "=r"(a) : "l"(p));
    return a;
}
static __device__ __forceinline__ u32 packh2(float x, float y) {
    __half hx = __float2half_rn(x), hy = __float2half_rn(y);
    return (u32)__half_as_ushort(hx) | ((u32)__half_as_ushort(hy) << 16);
}

#define LDSM4(r0, r1, r2, r3, a)                                             \
    asm volatile("ldmatrix.sync.aligned.m8n8.x4.shared.b16 {%0,%1,%2,%3}, [%4];" \
                 : "=r"(r0), "=r"(r1), "=r"(r2), "=r"(r3) : "r"(a))
#define MMAH(d, a0, a1, a2, a3, b0, b1)                                      \
    asm volatile("mma.sync.aligned.m16n8k16.row.col.f32.f16.f16.f32 "        \
                 "{%0,%1,%2,%3}, {%4,%5,%6,%7}, {%8,%9}, {%0,%1,%2,%3};"     \
                 : "+f"((d)[0]), "+f"((d)[1]), "+f"((d)[2]), "+f"((d)[3])    \
                 : "r"(a0), "r"(a1), "r"(a2), "r"(a3), "r"(b0), "r"(b1))

// ---------------- k_edge smem layout (bytes) ----------------
#define SO_W1T   0         // [128h][192k] fp16, stride 400 (51200), k-order [ea|dst|src]
#define SO_W2T   51200     // [64c][128k] fp16, stride 272  (17408)
#define SO_SB1   68608     // float[128]
#define SO_SB2   69120     // float[64]
#define SO_SEB   69376     // u64[32]
#define SO_SGP   69632
#define SO_SBBP  69888
#define SO_SGE   70144     // float[64] (conv0: next-layer edge LN gamma)
#define SO_SBE   70400     // float[64]
#define SO_EEW   70656     // u64[512]
#define SO_WARP  74752     // per-warp regions
#define PW_BYTES 7936
#define PO_A     0         // [16e][192k] fp16, stride 400 (6400); ndt aliases
#define PO_HB    6400      // 2 slots x 768
#define NWARPS_E 12
#define SM_EDGE_BYTES (74752 + NWARPS_E * PW_BYTES)   // 169984

// ---------------- zero accumulators ----------------
__global__ void k_zero() {
    int i = blockIdx.x * blockDim.x + threadIdx.x;
    if (i < NN * 128 / 4) {
        float4 z = make_float4(0.f, 0.f, 0.f, 0.f);
        ((float4*)g_nd0)[i] = z;
        ((float4*)g_nd1)[i] = z;
    }
}

// ---------------- node encoder (also writes fp16 features) ----------------
__global__ void __launch_bounds__(256) k_encode(
    const float* __restrict__ x, const float* __restrict__ enc_w,
    const float* __restrict__ enc_b, const float* __restrict__ enc_g,
    const float* __restrict__ enc_bb)
{
    extern __shared__ float sm[];
    for (int i = threadIdx.x; i < 96 * 64; i += blockDim.x) sm[i] = enc_w[i];
    __syncthreads();
    int l = threadIdx.x & 31;
    int warp = (blockIdx.x * blockDim.x + threadIdx.x) >> 5;
    int nwarps = (gridDim.x * blockDim.x) >> 5;
    float b0 = enc_b[l], b1v = enc_b[l + 32];
    float g0 = enc_g[l], g1 = enc_g[l + 32];
    float bb0 = enc_bb[l], bb1 = enc_bb[l + 32];
    for (int n = warp; n < NN; n += nwarps) {
        float xa = x[(size_t)n * 96 + l];
        float xb = x[(size_t)n * 96 + 32 + l];
        float xc = x[(size_t)n * 96 + 64 + l];
        float z0 = b0, z1 = b1v;
#pragma unroll 8
        for (int k = 0; k < 32; k++) {
            float xk = __shfl_sync(0xffffffffu, xa, k);
            z0 = fmaf(xk, sm[k * 64 + l], z0);
            z1 = fmaf(xk, sm[k * 64 + l + 32], z1);
        }
#pragma unroll 8
        for (int k = 0; k < 32; k++) {
            float xk = __shfl_sync(0xffffffffu, xb, k);
            z0 = fmaf(xk, sm[(k + 32) * 64 + l], z0);
            z1 = fmaf(xk, sm[(k + 32) * 64 + l + 32], z1);
        }
#pragma unroll 8
        for (int k = 0; k < 32; k++) {
            float xk = __shfl_sync(0xffffffffu, xc, k);
            z0 = fmaf(xk, sm[(k + 64) * 64 + l], z0);
            z1 = fmaf(xk, sm[(k + 64) * 64 + l + 32], z1);
        }
        float mu = wsum(z0 + z1) * (1.f / 64.f);
        float sq = wsum(z0 * z0 + z1 * z1) * (1.f / 64.f);
        float rs = rsqrtf(sq - mu * mu + 1e-5f);
        float xe0 = (z0 - mu) * rs * g0 + bb0;
        float xe1 = (z1 - mu) * rs * g1 + bb1;
        g_xenc[n * 64 + l]      = xe0;
        g_xenc[n * 64 + l + 32] = xe1;
        g_x16[n * 64 + l]      = __float2half_rn(xe0);
        g_x16[n * 64 + l + 32] = __float2half_rn(xe1);
    }
}

// ---------------- mma.sync edge kernel: K=192 fused node+edge GEMM ----------------
// conv0: phase-A computes LN(edge-enc); epilogue2 also writes LN(msg) fp16 for conv1.
// conv1: A-tile ea part is a coalesced copy of g_msg16.
__global__ void __launch_bounds__(384) k_edge(
    int conv, const int* __restrict__ ei, const float* __restrict__ eattr,
    const float* __restrict__ eenc_w, const float* __restrict__ eenc_b,
    const float* __restrict__ ln_g, const float* __restrict__ ln_b,
    const float* __restrict__ nge, const float* __restrict__ nbe,   // conv0: l1_eg / l1_eb
    const float* __restrict__ w1, const float* __restrict__ b1,
    const float* __restrict__ w2, const float* __restrict__ b2,
    const float* __restrict__ tptr)
{
    extern __shared__ __align__(1024) char smraw[];
    const u32 sb = smem_u32(smraw);
    int tid = threadIdx.x;
    int wid = tid >> 5, lane = tid & 31;

    u64* seb  = (u64*)(smraw + SO_SEB);
    u64* sgp  = (u64*)(smraw + SO_SGP);
    u64* sbbp = (u64*)(smraw + SO_SBBP);
    u64* eewp = (u64*)(smraw + SO_EEW);
    float* sb1 = (float*)(smraw + SO_SB1);
    float* sb2 = (float*)(smraw + SO_SB2);
    float* sge = (float*)(smraw + SO_SGE);
    float* sbe = (float*)(smraw + SO_SBE);

    // ---- one-time staging: fp16 weights; W1^T k-order = [ea | dst | src] ----
    for (int i = tid; i < 128 * 192; i += 384) {       // i = k*128 + h
        int k = i >> 7, h = i & 127;
        int srow = (k < 64) ? (128 + k) : (k - 64);
        *(u16*)(smraw + SO_W1T + h * 400 + k * 2) =
            __half_as_ushort(__float2half_rn(w1[srow * 128 + h]));
    }
    for (int i = tid; i < 128 * 64; i += 384) {        // W2^T [c][k], stride 272
        int k = i >> 6, c = i & 63;
        *(u16*)(smraw + SO_W2T + c * 272 + k * 2) =
            __half_as_ushort(__float2half_rn(w2[k * 64 + c]));
    }
    if (conv == 0) {
        for (int i = tid; i < 512; i += 384) eewp[i] = ((const u64*)eenc_w)[i];
        if (tid < 32) seb[tid] = ((const u64*)eenc_b)[tid];
        if (tid < 64) { sge[tid] = nge[tid]; sbe[tid] = nbe[tid]; }
        if (tid >= 64 && tid < 96) {
            sgp[tid - 64]  = ((const u64*)ln_g)[tid - 64];
            sbbp[tid - 64] = ((const u64*)ln_b)[tid - 64];
        }
    }
    if (tid < 128) sb1[tid] = b1[tid];
    if (tid < 64)  sb2[tid] = b2[tid];
    __syncthreads();

    const float t = tptr[0];
    const int* srcp = ei;
    const int* dstp = ei + NE;
    float* ndb = conv ? g_nd1 : g_nd0;
    const char* x16c = (const char*)g_x16;
    const char* msg16c = (const char*)g_msg16;

    char* pw_c = smraw + SO_WARP + wid * PW_BYTES;
    const u32 pwb  = sb + SO_WARP + wid * PW_BYTES;
    const u32 a_b  = pwb + PO_A;
    const u32 hb_b = pwb + PO_HB;
    float* ndt = (float*)(pw_c + PO_A);   // aliases A tile (dead after GEMM1)

    const int el = lane >> 1, half = lane & 1;
    const int r0 = lane >> 2, tp = lane & 3;
    const int hl = ((lane >> 4) << 3) | (lane & 7);
    const int khalf = (lane >> 3) & 1;
    const u32 aoff_a = (u32)((lane & 15) * 400 + (lane >> 4) * 16);
    const u32 boff4_w1 = (u32)(hl * 400 + khalf * 16);
    const u32 boff4_w2 = (u32)(hl * 272 + khalf * 16);
    const u32 aoff_hb = (u32)((lane & 15) * 48 + (lane >> 4) * 16);

    const int gw = blockIdx.x * NWARPS_E + wid;
    const int nw = gridDim.x * NWARPS_E;
    for (int g = gw; g < NE / 16; g += nw) {
        const int e16 = g * 16;
        // ---------- phase A (conv0 only): edge-enc + LN -> A[k 0..63] fp16 ----------
        if (conv == 0) {
            u64 z[16];
            float ar[16];
            const float4* ap = (const float4*)(eattr + (size_t)(e16 + el) * 16);
            *(float4*)&ar[0]  = ap[0]; *(float4*)&ar[4]  = ap[1];
            *(float4*)&ar[8]  = ap[2]; *(float4*)&ar[12] = ap[3];
#pragma unroll
            for (int j = 0; j < 16; j++) z[j] = seb[half * 16 + j];
#pragma unroll
            for (int k = 0; k < 16; k++) {
                u64 av = pack2(ar[k], ar[k]);
                const ulonglong2* wr2 = (const ulonglong2*)(eewp + k * 32 + half * 16);
#pragma unroll
                for (int j = 0; j < 8; j++) {
                    ulonglong2 w = wr2[j];
                    z[2 * j]     = fma2(av, w.x, z[2 * j]);
                    z[2 * j + 1] = fma2(av, w.y, z[2 * j + 1]);
                }
            }
            u64 s2 = 0ull, q2 = 0ull;
#pragma unroll
            for (int j = 0; j < 16; j++) { s2 = add2(s2, z[j]); q2 = fma2(z[j], z[j], q2); }
            float sl, sh2, ql, qh;
            unpack2(s2, sl, sh2); unpack2(q2, ql, qh);
            float ps = sl + sh2, pq = ql + qh;
            ps += __shfl_xor_sync(0xffffffffu, ps, 1);
            pq += __shfl_xor_sync(0xffffffffu, pq, 1);
            float mu = ps * (1.f / 64.f);
            float rs = rsqrtf(pq * (1.f / 64.f) - mu * mu + 1e-5f);
            u64 nmu2 = pack2(-mu, -mu), rs2 = pack2(rs, rs);
#pragma unroll
            for (int j = 0; j < 16; j++) {
                u64 cen = mul2(add2(z[j], nmu2), rs2);
                u64 v = fma2(cen, sgp[half * 16 + j], sbbp[half * 16 + j]);
                float lo, hi; unpack2(v, lo, hi);
                int ch = half * 32 + 2 * j;
                *(u32*)(pw_c + PO_A + el * 400 + ch * 2) = packh2(lo, hi);
            }
        }
        // ---------- gather: coalesced fp16 rows into A (+ ea copy for conv1) ----------
#pragma unroll 4
        for (int r = 0; r < 16; r++) {
            int d = dstp[e16 + r], s = srcp[e16 + r];   // warp-uniform
            if (conv) {
                u32 vm = *(const u32*)(msg16c + (size_t)(e16 + r) * 128 + 4 * lane);
                *(u32*)(pw_c + PO_A + r * 400 + 4 * lane) = vm;
            }
            u32 vd = *(const u32*)(x16c + (size_t)d * 128 + 4 * lane);
            u32 vs = *(const u32*)(x16c + (size_t)s * 128 + 4 * lane);
            *(u32*)(pw_c + PO_A + r * 400 + 128 + 4 * lane) = vd;
            *(u32*)(pw_c + PO_A + r * 400 + 256 + 4 * lane) = vs;
        }
        __syncwarp();
        // ---------- GEMM1: D1[16e][128h] = A[16e][192k] @ W1^T ----------
        float d1[16][4];
#pragma unroll
        for (int nt = 0; nt < 16; nt++) { d1[nt][0] = d1[nt][1] = d1[nt][2] = d1[nt][3] = 0.f; }
#pragma unroll
        for (int kc = 0; kc < 12; kc++) {
            u32 ah0, ah1, ah2, ah3;
            LDSM4(ah0, ah1, ah2, ah3, a_b + kc * 32 + aoff_a);
#pragma unroll
            for (int p = 0; p < 8; p++) {
                u32 bh0, bh1, bh2, bh3;
                LDSM4(bh0, bh1, bh2, bh3,
                      sb + SO_W1T + (u32)(p * 6400 + kc * 32) + boff4_w1);
                MMAH(d1[2 * p],     ah0, ah1, ah2, ah3, bh0, bh1);
                MMAH(d1[2 * p + 1], ah0, ah1, ah2, ah3, bh2, bh3);
            }
        }
        __syncwarp();
        // ---------- fused epilogue1 (+b1, relu) + GEMM2 ----------
        float d2[8][4];
#pragma unroll
        for (int ct = 0; ct < 8; ct++) { d2[ct][0] = d2[ct][1] = d2[ct][2] = d2[ct][3] = 0.f; }
#pragma unroll
        for (int hc = 0; hc < 8; hc++) {
            int n0 = 2 * hc, n1 = 2 * hc + 1;
            u32 slot = (hc & 1) ? 768u : 0u;
            float2 bA = *(const float2*)(sb1 + hc * 16 + 2 * tp);
            float2 bB = *(const float2*)(sb1 + hc * 16 + 8 + 2 * tp);
#pragma unroll
            for (int rr = 0; rr < 2; rr++) {
                int r = r0 + 8 * rr;
                float v0 = fmaxf(d1[n0][2 * rr]     + bA.x, 0.f);
                float v1 = fmaxf(d1[n0][2 * rr + 1] + bA.y, 0.f);
                float v2 = fmaxf(d1[n1][2 * rr]     + bB.x, 0.f);
                float v3 = fmaxf(d1[n1][2 * rr + 1] + bB.y, 0.f);
                char* hrow = pw_c + PO_HB + slot + r * 48;
                *(u32*)(hrow + 4 * tp)      = packh2(v0, v1);
                *(u32*)(hrow + 16 + 4 * tp) = packh2(v2, v3);
            }
            __syncwarp();
            u32 ah0, ah1, ah2, ah3;
            LDSM4(ah0, ah1, ah2, ah3, hb_b + slot + aoff_hb);
#pragma unroll
            for (int q = 0; q < 4; q++) {
                u32 bh0, bh1, bh2, bh3;
                LDSM4(bh0, bh1, bh2, bh3,
                      sb + SO_W2T + (u32)(q * 4352 + hc * 32) + boff4_w2);
                MMAH(d2[2 * q],     ah0, ah1, ah2, ah3, bh0, bh1);
                MMAH(d2[2 * q + 1], ah0, ah1, ah2, ah3, bh2, bh3);
            }
            __syncwarp();
        }
        __syncwarp();   // A dead; ndt (aliased) safe to write
        // ---------- epilogue2: + b2, exp -> RED; conv0 also LN(msg) -> g_msg16 ----------
#pragma unroll
        for (int rr = 0; rr < 2; rr++) {
            int r = r0 + 8 * rr;
            int e = e16 + r;
            float ms[16];
            float s = 0.f, q = 0.f;
#pragma unroll
            for (int ct = 0; ct < 8; ct++) {
                int c0 = 8 * ct + 2 * tp;
                float m0 = d2[ct][2 * rr]     + sb2[c0];
                float m1 = d2[ct][2 * rr + 1] + sb2[c0 + 1];
                ms[2 * ct] = m0; ms[2 * ct + 1] = m1;
                float E0 = __expf(m0 * t), E1 = __expf(m1 * t);
                *(float4*)(ndt + r0 * 136 + 2 * c0) = make_float4(m0 * E0, E0, m1 * E1, E1);
                s += m0 + m1;
                q = fmaf(m0, m0, q); q = fmaf(m1, m1, q);
            }
            if (conv == 0) {
                s += __shfl_xor_sync(0xffffffffu, s, 1);
                s += __shfl_xor_sync(0xffffffffu, s, 2);
                q += __shfl_xor_sync(0xffffffffu, q, 1);
                q += __shfl_xor_sync(0xffffffffu, q, 2);
                float mu = s * (1.f / 64.f);
                float rsg = rsqrtf(q * (1.f / 64.f) - mu * mu + 1e-5f);
#pragma unroll
                for (int ct = 0; ct < 8; ct++) {
                    int c0 = 8 * ct + 2 * tp;
                    float e0 = (ms[2 * ct]     - mu) * rsg * sge[c0]     + sbe[c0];
                    float e1 = (ms[2 * ct + 1] - mu) * rsg * sge[c0 + 1] + sbe[c0 + 1];
                    *(u32*)((char*)g_msg16 + (size_t)e * 128 + c0 * 2) = packh2(e0, e1);
                }
            }
            __syncwarp();
#pragma unroll 4
            for (int eb = 0; eb < 8; eb++) {
                int d = dstp[e16 + 8 * rr + eb];        // warp-uniform broadcast
                float4 v = *(const float4*)(ndt + eb * 136 + 4 * lane);
                asm volatile("red.global.add.v4.f32 [%0], {%1,%2,%3,%4};"
                             :: "l"(ndb + (size_t)d * 128 + 4 * lane),
                                "f"(v.x), "f"(v.y), "f"(v.z), "f"(v.w) : "memory");
            }
            __syncwarp();
        }
    }
}

// ---------------- conv0 node finish (also writes fp16 h) ----------------
__global__ void __launch_bounds__(256) k_node0(
    const float* __restrict__ wr, const float* __restrict__ lg, const float* __restrict__ lb)
{
    extern __shared__ float sm[];
    for (int i = threadIdx.x; i < 64 * 64; i += blockDim.x) sm[i] = wr[i];
    __syncthreads();
    int l = threadIdx.x & 31;
    int warp = (blockIdx.x * blockDim.x + threadIdx.x) >> 5;
    int nwarps = (gridDim.x * blockDim.x) >> 5;
    float g0 = lg[l], g1 = lg[l + 32], b0 = lb[l], b1v = lb[l + 32];
    for (int n = warp; n < NN; n += nwarps) {
        float xe0 = g_xenc[n * 64 + l], xe1 = g_xenc[n * 64 + 32 + l];
        float r0 = 0.f, r1 = 0.f;
#pragma unroll 8
        for (int k = 0; k < 32; k++) {
            float xk = __shfl_sync(0xffffffffu, xe0, k);
            r0 = fmaf(xk, sm[k * 64 + l], r0);
            r1 = fmaf(xk, sm[k * 64 + l + 32], r1);
        }
#pragma unroll 8
        for (int k = 0; k < 32; k++) {
            float xk = __shfl_sync(0xffffffffu, xe1, k);
            r0 = fmaf(xk, sm[(k + 32) * 64 + l], r0);
            r1 = fmaf(xk, sm[(k + 32) * 64 + l + 32], r1);
        }
        float2 na = *(const float2*)(g_nd0 + (size_t)n * 128 + 2 * l);
        float2 nb = *(const float2*)(g_nd0 + (size_t)n * 128 + 64 + 2 * l);
        float x10 = ((na.y != 0.f) ? na.x / na.y : 0.f) + r0;
        float x11 = ((nb.y != 0.f) ? nb.x / nb.y : 0.f) + r1;
        g_x1[n * 64 + l] = x10;
        g_x1[n * 64 + l + 32] = x11;
        float mu = wsum(x10 + x11) * (1.f / 64.f);
        float sq = wsum(x10 * x10 + x11 * x11) * (1.f / 64.f);
        float rs = rsqrtf(sq - mu * mu + 1e-5f);
        float h0 = fmaxf((x10 - mu) * rs * g0 + b0, 0.f);
        float h1 = fmaxf((x11 - mu) * rs * g1 + b1v, 0.f);
        g_h1[n * 64 + l]      = h0;
        g_h1[n * 64 + l + 32] = h1;
        g_x16[n * 64 + l]      = __float2half_rn(h0);
        g_x16[n * 64 + l + 32] = __float2half_rn(h1);
    }
}

// ---------------- final node kernel ----------------
__global__ void __launch_bounds__(256) k_node1(
    const float* __restrict__ wr, float* __restrict__ out)
{
    extern __shared__ float sm[];
    for (int i = threadIdx.x; i < 64 * 64; i += blockDim.x) sm[i] = wr[i];
    __syncthreads();
    int l = threadIdx.x & 31;
    int warp = (blockIdx.x * blockDim.x + threadIdx.x) >> 5;
    int nwarps = (gridDim.x * blockDim.x) >> 5;
    for (int n = warp; n < NN; n += nwarps) {
        float he0 = g_h1[n * 64 + l], he1 = g_h1[n * 64 + 32 + l];
        float r0 = 0.f, r1 = 0.f;
#pragma unroll 8
        for (int k = 0; k < 32; k++) {
            float xk = __shfl_sync(0xffffffffu, he0, k);
            r0 = fmaf(xk, sm[k * 64 + l], r0);
            r1 = fmaf(xk, sm[k * 64 + l + 32], r1);
        }
#pragma unroll 8
        for (int k = 0; k < 32; k++) {
            float xk = __shfl_sync(0xffffffffu, he1, k);
            r0 = fmaf(xk, sm[(k + 32) * 64 + l], r0);
            r1 = fmaf(xk, sm[(k + 32) * 64 + l + 32], r1);
        }
        float2 na = *(const float2*)(g_nd1 + (size_t)n * 128 + 2 * l);
        float2 nb = *(const float2*)(g_nd1 + (size_t)n * 128 + 64 + 2 * l);
        float a0 = ((na.y != 0.f) ? na.x / na.y : 0.f) + r0;
        float a1 = ((nb.y != 0.f) ? nb.x / nb.y : 0.f) + r1;
        out[n * 64 + l]      = g_x1[n * 64 + l] + a0;
        out[n * 64 + l + 32] = g_x1[n * 64 + l + 32] + a1;
    }
}

extern "C" void kernel_launch(void* const* d_in, const int* in_sizes, int n_in,
                              void* d_out, int out_size)
{
    const float* x       = (const float*)d_in[0];
    const int*   ei      = (const int*)  d_in[1];
    const float* eattr   = (const float*)d_in[2];
    const float* enc_w   = (const float*)d_in[3];
    const float* enc_b   = (const float*)d_in[4];
    const float* enc_g   = (const float*)d_in[5];
    const float* enc_bb  = (const float*)d_in[6];
    const float* eenc_w  = (const float*)d_in[7];
    const float* eenc_b  = (const float*)d_in[8];
    const float* eenc_g  = (const float*)d_in[9];
    const float* eenc_bb = (const float*)d_in[10];
    const float* c0_w1   = (const float*)d_in[11];
    const float* c0_b1   = (const float*)d_in[12];
    const float* c0_w2   = (const float*)d_in[13];
    const float* c0_b2   = (const float*)d_in[14];
    const float* c0_wr   = (const float*)d_in[15];
    const float* c0_t    = (const float*)d_in[16];
    const float* l1_g    = (const float*)d_in[17];
    const float* l1_b    = (const float*)d_in[18];
    const float* l1_eg   = (const float*)d_in[19];
    const float* l1_eb   = (const float*)d_in[20];
    const float* c1_w1   = (const float*)d_in[21];
    const float* c1_b1   = (const float*)d_in[22];
    const float* c1_w2   = (const float*)d_in[23];
    const float* c1_b2   = (const float*)d_in[24];
    const float* c1_wr   = (const float*)d_in[25];
    const float* c1_t    = (const float*)d_in[26];
    float* out = (float*)d_out;

    cudaFuncSetAttribute(k_edge, cudaFuncAttributeMaxDynamicSharedMemorySize, SM_EDGE_BYTES);

    k_zero<<<2500, 256>>>();
    k_encode<<<320, 256, 24576>>>(x, enc_w, enc_b, enc_g, enc_bb);
    k_edge<<<148, 384, SM_EDGE_BYTES>>>(0, ei, eattr, eenc_w, eenc_b, eenc_g, eenc_bb,
                                        l1_eg, l1_eb,
                                        c0_w1, c0_b1, c0_w2, c0_b2, c0_t);
    k_node0<<<320, 256, 16384>>>(c0_wr, l1_g, l1_b);
    k_edge<<<148, 384, SM_EDGE_BYTES>>>(1, ei, eattr, eenc_w, eenc_b, l1_eg, l1_eb,
                                        l1_eg, l1_eb,
                                        c1_w1, c1_b1, c1_w2, c1_b2, c1_t);
    k_node1<<<320, 256, 16384>>>(c1_wr, out);
}